// round 2
// baseline (speedup 1.0000x reference)
#include <cuda_runtime.h>
#include <cstdint>

#define BATCH 8
#define CCH   48
#define NPIX  4096
#define NB    32768           // BATCH * NPIX
#define KNN   9
#define MSPLIT 4

// ---------------- scratch (device globals; no allocation allowed) ----------------
__device__ float4 g_xn[NB * 12];     // normalized features, node-major [NB][48]
__device__ float4 g_nodes[NB * 12];  // raw features, node-major [NB][48]
__device__ float  g_sq[NB];          // sum(xn^2) per node
__device__ float  g_pd[NB * MSPLIT * KNN];
__device__ int    g_pi[NB * MSPLIT * KNN];
__device__ int    g_knn[NB * KNN];   // final sorted neighbor list (global node ids)
__device__ int    g_deg[NB];

// ---------------- f32x2 packed helpers (sm_103a) ----------------
__device__ __forceinline__ unsigned long long ffma2(unsigned long long a,
                                                    unsigned long long b,
                                                    unsigned long long c) {
    unsigned long long d;
    asm("fma.rn.f32x2 %0, %1, %2, %3;" : "=l"(d) : "l"(a), "l"(b), "l"(c));
    return d;
}
__device__ __forceinline__ unsigned long long fadd2(unsigned long long a,
                                                    unsigned long long b) {
    unsigned long long d;
    asm("add.rn.f32x2 %0, %1, %2;" : "=l"(d) : "l"(a), "l"(b));
    return d;
}

// ======================================================================
// K1: transpose (B,C,N) -> node-major, L2-normalize over channels,
//     compute sq = sum(xn^2), zero degree counters.
// ======================================================================
__global__ __launch_bounds__(128) void k1_normalize(const float* __restrict__ x) {
    __shared__ float s[128 * 49];   // padded rows: 49 to kill bank conflicts
    __shared__ float s_mn[128];
    const int tid  = threadIdx.x;
    const int n0g  = blockIdx.x * 128;          // global node base
    const int b    = n0g >> 12;                 // /4096
    const int nloc = n0g & (NPIX - 1);

    // load: x[b, c, nloc+tid] -> s[tid][c]
    const float* xb = x + (size_t)b * CCH * NPIX + nloc;
    #pragma unroll
    for (int c = 0; c < CCH; c++)
        s[tid * 49 + c] = xb[(size_t)c * NPIX + tid];

    // per-row norm + sq
    float ss = 0.f;
    #pragma unroll
    for (int c = 0; c < CCH; c++) { float v = s[tid * 49 + c]; ss += v * v; }
    float mn = fmaxf(sqrtf(ss), 1e-12f);
    s_mn[tid] = mn;
    float sqv = 0.f;
    #pragma unroll
    for (int c = 0; c < CCH; c++) { float v = s[tid * 49 + c] / mn; sqv += v * v; }
    g_sq[n0g + tid]  = sqv;
    g_deg[n0g + tid] = 0;
    __syncthreads();

    // coalesced transposed writes
    float* nodes_f = (float*)g_nodes;
    float* xn_f    = (float*)g_xn;
    #pragma unroll
    for (int it = 0; it < 48; it++) {
        int idx = it * 128 + tid;
        int q = idx / 48, rr = idx - q * 48;
        float v = s[q * 49 + rr];
        nodes_f[(size_t)n0g * 48 + idx] = v;
        xn_f[(size_t)n0g * 48 + idx]    = v / s_mn[q];
    }
}

// ======================================================================
// K2: brute-force KNN. Each block: 128 rows (one per thread) x 1024 cols
//     (one quarter of the batch). Per-thread sorted top-9 kept in registers.
//     Dot products via packed fma.rn.f32x2 (2 channels / instr).
// ======================================================================
__global__ __launch_bounds__(128, 4) void k2_knn() {
    const int tid     = threadIdx.x;
    const int r       = blockIdx.x * 128 + tid;   // global row node
    const int quarter = blockIdx.y;
    const int b       = r >> 12;

    __shared__ float4 tile[128 * 12];
    __shared__ float  sqs[128];

    ulonglong2 A[12];
    {
        const ulonglong2* ap = (const ulonglong2*)(g_xn + (size_t)r * 12);
        #pragma unroll
        for (int q = 0; q < 12; q++) A[q] = ap[q];
    }
    const float sqn = g_sq[r];

    float d9[KNN];
    int   i9[KNN];
    #pragma unroll
    for (int k = 0; k < KNN; k++) { d9[k] = __int_as_float(0x7f800000); i9[k] = 0x7fffffff; }

    const int mbase = b * NPIX + quarter * 1024;
    for (int t = 0; t < 8; t++) {
        const int g0 = mbase + t * 128;
        const float4* src = g_xn + (size_t)g0 * 12;
        #pragma unroll
        for (int i = 0; i < 12; i++) tile[i * 128 + tid] = src[i * 128 + tid];
        sqs[tid] = g_sq[g0 + tid];
        __syncthreads();

        for (int j = 0; j < 128; j++) {
            const ulonglong2* p = (const ulonglong2*)(tile + j * 12);
            unsigned long long a0 = 0ull, a1 = 0ull, a2 = 0ull, a3 = 0ull;
            #pragma unroll
            for (int q = 0; q < 12; q += 2) {
                ulonglong2 b0 = p[q];
                ulonglong2 b1 = p[q + 1];
                a0 = ffma2(A[q].x,     b0.x, a0);
                a1 = ffma2(A[q].y,     b0.y, a1);
                a2 = ffma2(A[q + 1].x, b1.x, a2);
                a3 = ffma2(A[q + 1].y, b1.y, a3);
            }
            a0 = fadd2(a0, a1);
            a2 = fadd2(a2, a3);
            a0 = fadd2(a0, a2);
            float lo, hi;
            asm("mov.b64 {%0,%1}, %2;" : "=f"(lo), "=f"(hi) : "l"(a0));
            const float dot = lo + hi;
            const float d   = (sqn + sqs[j]) - 2.0f * dot;
            const int   m   = g0 + j;
            if (d < d9[KNN - 1]) {               // strict: ties keep lower index
                d9[KNN - 1] = d; i9[KNN - 1] = m;
                #pragma unroll
                for (int k = KNN - 1; k > 0; --k) {
                    if (d9[k] < d9[k - 1]) {     // strict: stable for equal dists
                        float td = d9[k]; d9[k] = d9[k - 1]; d9[k - 1] = td;
                        int   ti = i9[k]; i9[k] = i9[k - 1]; i9[k - 1] = ti;
                    }
                }
            }
        }
        __syncthreads();
    }

    const int base = (r * MSPLIT + quarter) * KNN;
    #pragma unroll
    for (int k = 0; k < KNN; k++) { g_pd[base + k] = d9[k]; g_pi[base + k] = i9[k]; }
}

// ======================================================================
// K3: 4-way merge of sorted partial top-9 lists, lexicographic (dist, idx).
// ======================================================================
__global__ void k3_merge() {
    const int i = blockIdx.x * 256 + threadIdx.x;
    if (i >= NB) return;
    float d[MSPLIT][KNN];
    int   ix[MSPLIT][KNN];
    int   h[MSPLIT];
    #pragma unroll
    for (int q = 0; q < MSPLIT; q++) {
        h[q] = 0;
        const int base = (i * MSPLIT + q) * KNN;
        #pragma unroll
        for (int k = 0; k < KNN; k++) { d[q][k] = g_pd[base + k]; ix[q][k] = g_pi[base + k]; }
    }
    #pragma unroll
    for (int k = 0; k < KNN; k++) {
        float bd = __int_as_float(0x7f800000);
        int   bi = 0x7fffffff, bq = 0;
        #pragma unroll
        for (int q = 0; q < MSPLIT; q++) {
            if (h[q] < KNN) {
                float dd = d[q][h[q]];
                int   ii = ix[q][h[q]];
                if (dd < bd || (dd == bd && ii < bi)) { bd = dd; bi = ii; bq = q; }
            }
        }
        g_knn[i * KNN + k] = bi;
        h[bq]++;
    }
}

// ======================================================================
// K4: degree counting by src (the linspace quirk == drop the final edge).
// ======================================================================
__global__ void k4_degree() {
    const int e = blockIdx.x * 256 + threadIdx.x;
    if (e >= NB * KNN) return;
    if (e == NB * KNN - 1) return;               // dropped tail edge
    atomicAdd(&g_deg[g_knn[e]], 1);
}

// ======================================================================
// K5: fused Tx1 gather + both GEMMs + bias.
//   t1[i]  = -dinv[i] * sum_k dinv[src_k] * nodes[src_k]
//   out[i] = nodes[i] @ W0 + t1 @ W1 + bias
// 4 nodes per block, thread = (local node, output channel).
// ======================================================================
__global__ __launch_bounds__(192) void k5_output(const float* __restrict__ W0,
                                                 const float* __restrict__ W1,
                                                 const float* __restrict__ bias,
                                                 float* __restrict__ out) {
    const int node0 = blockIdx.x * 4;
    const int ln = threadIdx.x / 48;
    const int c  = threadIdx.x - ln * 48;
    const int i  = node0 + ln;

    __shared__ float t1[4][48];
    __shared__ int   ssrc[4][KNN];
    __shared__ float sdi[4][KNN];

    if (threadIdx.x < 4 * KNN) {
        const int l = threadIdx.x / KNN, k = threadIdx.x - l * KNN;
        const int e = (node0 + l) * KNN + k;
        const int s = g_knn[e];
        ssrc[l][k] = s;
        float di = 0.f;
        const int dg = g_deg[s];
        if (dg > 0 && e != NB * KNN - 1) di = rsqrtf((float)dg);
        sdi[l][k] = di;
    }
    __syncthreads();

    const float* nodes = (const float*)g_nodes;
    float acc = 0.f;
    #pragma unroll
    for (int k = 0; k < KNN; k++)
        acc += sdi[ln][k] * nodes[(size_t)ssrc[ln][k] * 48 + c];

    const int dgi = g_deg[i];
    const float dinv_i = (dgi > 0) ? rsqrtf((float)dgi) : 0.f;
    t1[ln][c] = -dinv_i * acc;
    __syncthreads();

    float o = bias[c];
    const float* nrow = nodes + (size_t)i * 48;
    #pragma unroll
    for (int cc = 0; cc < 48; cc++)
        o += nrow[cc] * W0[cc * 48 + c] + t1[ln][cc] * W1[cc * 48 + c];
    out[(size_t)i * 48 + c] = o;
}

// ======================================================================
extern "C" void kernel_launch(void* const* d_in, const int* in_sizes, int n_in,
                              void* d_out, int out_size) {
    const float* x    = (const float*)d_in[0];   // (8,48,64,64)
    const float* W0   = (const float*)d_in[1];   // (48,48)
    const float* W1   = (const float*)d_in[2];   // (48,48)
    const float* bias = (const float*)d_in[3];   // (48,)
    float* out = (float*)d_out;                  // (32768,48)

    k1_normalize<<<NB / 128, 128>>>(x);
    k2_knn<<<dim3(NB / 128, MSPLIT), 128>>>();
    k3_merge<<<(NB + 255) / 256, 256>>>();
    k4_degree<<<(NB * KNN + 255) / 256, 256>>>();
    k5_output<<<NB / 4, 192>>>(W0, W1, bias, out);
}

// round 3
// speedup vs baseline: 1.0005x; 1.0005x over previous
#include <cuda_runtime.h>
#include <cstdint>

#define BATCH 8
#define CCH   48
#define NPIX  4096
#define NB    32768           // BATCH * NPIX
#define KNN   9
#define TCOLS 128             // column tile per smem buffer

// ---------------- scratch (device globals; no allocation allowed) ----------------
__device__ float4 g_xn[NB * 12];     // normalized features, node-major [NB][48]
__device__ float4 g_nodes[NB * 12];  // raw features, node-major [NB][48]
__device__ float  g_sq[NB];          // sum(xn^2) per node
__device__ int    g_knn[NB * KNN];   // final sorted neighbor list (global node ids)
__device__ int    g_deg[NB];

// ---------------- f32x2 packed helpers (sm_103a) ----------------
__device__ __forceinline__ unsigned long long ffma2(unsigned long long a,
                                                    unsigned long long b,
                                                    unsigned long long c) {
    unsigned long long d;
    asm("fma.rn.f32x2 %0, %1, %2, %3;" : "=l"(d) : "l"(a), "l"(b), "l"(c));
    return d;
}
__device__ __forceinline__ unsigned long long fadd2(unsigned long long a,
                                                    unsigned long long b) {
    unsigned long long d;
    asm("add.rn.f32x2 %0, %1, %2;" : "=l"(d) : "l"(a), "l"(b));
    return d;
}
__device__ __forceinline__ uint32_t smem_u32(const void* p) {
    uint32_t a;
    asm("{ .reg .u64 t; cvta.to.shared.u64 t, %1; cvt.u32.u64 %0, t; }" : "=r"(a) : "l"(p));
    return a;
}
__device__ __forceinline__ void cp16(uint32_t dst, const void* src) {
    asm volatile("cp.async.cg.shared.global [%0], [%1], 16;" :: "r"(dst), "l"(src));
}
__device__ __forceinline__ void cp4(uint32_t dst, const void* src) {
    asm volatile("cp.async.ca.shared.global [%0], [%1], 4;" :: "r"(dst), "l"(src));
}
__device__ __forceinline__ void cp_commit() {
    asm volatile("cp.async.commit_group;");
}
template <int N>
__device__ __forceinline__ void cp_wait() {
    asm volatile("cp.async.wait_group %0;" :: "n"(N));
}

// ======================================================================
// K1: transpose (B,C,N) -> node-major, L2-normalize over channels,
//     compute sq = sum(xn^2), zero degree counters.
// ======================================================================
__global__ __launch_bounds__(128) void k1_normalize(const float* __restrict__ x) {
    __shared__ float s[128 * 49];   // padded rows: 49 to kill bank conflicts
    __shared__ float s_rmn[128];
    const int tid  = threadIdx.x;
    const int n0g  = blockIdx.x * 128;          // global node base
    const int b    = n0g >> 12;                 // /4096
    const int nloc = n0g & (NPIX - 1);

    // load: x[b, c, nloc+tid] -> s[tid][c]
    const float* xb = x + (size_t)b * CCH * NPIX + nloc;
    #pragma unroll
    for (int c = 0; c < CCH; c++)
        s[tid * 49 + c] = xb[(size_t)c * NPIX + tid];

    // per-row norm + sq
    float ss = 0.f;
    #pragma unroll
    for (int c = 0; c < CCH; c++) { float v = s[tid * 49 + c]; ss += v * v; }
    float mn  = fmaxf(sqrtf(ss), 1e-12f);
    float rmn = 1.0f / mn;
    s_rmn[tid] = rmn;
    float sqv = 0.f;
    #pragma unroll
    for (int c = 0; c < CCH; c++) { float v = s[tid * 49 + c] * rmn; sqv += v * v; }
    g_sq[n0g + tid]  = sqv;
    g_deg[n0g + tid] = 0;
    __syncthreads();

    // coalesced transposed writes
    float* nodes_f = (float*)g_nodes;
    float* xn_f    = (float*)g_xn;
    #pragma unroll
    for (int it = 0; it < 48; it++) {
        int idx = it * 128 + tid;
        int q = idx / 48, rr = idx - q * 48;
        float v = s[q * 49 + rr];
        nodes_f[(size_t)n0g * 48 + idx] = v;
        xn_f[(size_t)n0g * 48 + idx]    = v * s_rmn[q];
    }
}

// ======================================================================
// K2: brute-force KNN, one thread per row, full 4096-column scan.
//     Double-buffered cp.async column tiles; packed f32x2 dot products;
//     sorted top-9 in registers with branchless carry-insert.
//     Tail: write sorted neighbor list + degree atomics (fused old K4).
// ======================================================================
__global__ __launch_bounds__(128, 2) void k2_knn() {
    const int tid = threadIdx.x;
    const int r   = blockIdx.x * 128 + tid;     // global row node
    const int b   = r >> 12;

    __shared__ float4 tile[2][TCOLS * 12];
    __shared__ float  sqs[2][TCOLS];

    // row vector in registers (48 floats = 12 x ulonglong2)
    ulonglong2 A[12];
    {
        const ulonglong2* ap = (const ulonglong2*)(g_xn + (size_t)r * 12);
        #pragma unroll
        for (int q = 0; q < 12; q++) A[q] = ap[q];
    }

    // sorted ascending top-9 (d, idx)
    float d9[KNN];
    int   i9[KNN];
    #pragma unroll
    for (int k = 0; k < KNN; k++) { d9[k] = __int_as_float(0x7f800000); i9[k] = 0x7fffffff; }

    const int mbase = b * NPIX;
    const uint32_t s_tile0 = smem_u32(&tile[0][0]);
    const uint32_t s_tile1 = smem_u32(&tile[1][0]);
    const uint32_t s_sqs0  = smem_u32(&sqs[0][0]);
    const uint32_t s_sqs1  = smem_u32(&sqs[1][0]);

    // prefetch tile 0
    {
        const float4* src = g_xn + (size_t)mbase * 12;
        #pragma unroll
        for (int i = 0; i < 12; i++)
            cp16(s_tile0 + (i * 128 + tid) * 16, src + i * 128 + tid);
        cp4(s_sqs0 + tid * 4, g_sq + mbase + tid);
        cp_commit();
    }

    #pragma unroll 1
    for (int t = 0; t < NPIX / TCOLS; t++) {
        const int g0 = mbase + t * TCOLS;
        const int buf = t & 1;
        cp_wait<0>();
        __syncthreads();     // tile t visible to all; compute of t-1 finished everywhere

        // prefetch tile t+1 into the other buffer (overlaps with compute)
        if (t + 1 < NPIX / TCOLS) {
            const float4* src = g_xn + (size_t)(g0 + TCOLS) * 12;
            const uint32_t dt = buf ? s_tile0 : s_tile1;
            const uint32_t ds = buf ? s_sqs0  : s_sqs1;
            #pragma unroll
            for (int i = 0; i < 12; i++)
                cp16(dt + (i * 128 + tid) * 16, src + i * 128 + tid);
            cp4(ds + tid * 4, g_sq + g0 + TCOLS + tid);
            cp_commit();
        }

        const float4* tb = tile[buf];
        const float*  sb = sqs[buf];

        #pragma unroll 1
        for (int jb = 0; jb < TCOLS; jb += 4) {
            float dd[4];
            #pragma unroll
            for (int cc = 0; cc < 4; cc++) {
                const ulonglong2* p = (const ulonglong2*)(tb + (jb + cc) * 12);
                unsigned long long a0 = 0ull, a1 = 0ull;
                #pragma unroll
                for (int q = 0; q < 12; q++) {
                    ulonglong2 bv = p[q];
                    a0 = ffma2(A[q].x, bv.x, a0);
                    a1 = ffma2(A[q].y, bv.y, a1);
                }
                a0 = fadd2(a0, a1);
                float lo, hi;
                asm("mov.b64 {%0,%1}, %2;" : "=f"(lo), "=f"(hi) : "l"(a0));
                dd[cc] = sb[jb + cc] - 2.0f * (lo + hi);   // + sq[row] dropped: ordering-invariant
            }
            #pragma unroll
            for (int cc = 0; cc < 4; cc++) {
                const float v = dd[cc];
                if (v < d9[KNN - 1]) {
                    // branchless sorted carry-insert (strict <: stable, keeps lower index)
                    float cd = v; int ci = g0 + jb + cc;
                    #pragma unroll
                    for (int k = 0; k < KNN; k++) {
                        const bool sw = cd < d9[k];
                        const float td = d9[k]; const int ti = i9[k];
                        d9[k] = sw ? cd : td;  i9[k] = sw ? ci : ti;
                        cd    = sw ? td : cd;  ci    = sw ? ti : ci;
                    }
                }
            }
        }
        // no trailing barrier needed: next iteration's cp_wait+sync covers it
    }

    // write sorted neighbor list + fused degree counting
    #pragma unroll
    for (int k = 0; k < KNN; k++) {
        g_knn[r * KNN + k] = i9[k];
        // the linspace quirk drops exactly the final global edge (last node, rank-8)
        if (!(r == NB - 1 && k == KNN - 1))
            atomicAdd(&g_deg[i9[k]], 1);
    }
}

// ======================================================================
// K5: fused Tx1 gather + both GEMMs + bias.
//   t1[i]  = -dinv[i] * sum_k dinv[src_k] * nodes[src_k]
//   out[i] = nodes[i] @ W0 + t1 @ W1 + bias
// ======================================================================
__global__ __launch_bounds__(192) void k5_output(const float* __restrict__ W0,
                                                 const float* __restrict__ W1,
                                                 const float* __restrict__ bias,
                                                 float* __restrict__ out) {
    const int node0 = blockIdx.x * 4;
    const int ln = threadIdx.x / 48;
    const int c  = threadIdx.x - ln * 48;
    const int i  = node0 + ln;

    __shared__ float t1[4][48];
    __shared__ int   ssrc[4][KNN];
    __shared__ float sdi[4][KNN];

    if (threadIdx.x < 4 * KNN) {
        const int l = threadIdx.x / KNN, k = threadIdx.x - l * KNN;
        const int e = (node0 + l) * KNN + k;
        const int s = g_knn[e];
        ssrc[l][k] = s;
        float di = 0.f;
        const int dg = g_deg[s];
        if (dg > 0 && e != NB * KNN - 1) di = rsqrtf((float)dg);
        sdi[l][k] = di;
    }
    __syncthreads();

    const float* nodes = (const float*)g_nodes;
    float acc = 0.f;
    #pragma unroll
    for (int k = 0; k < KNN; k++)
        acc += sdi[ln][k] * nodes[(size_t)ssrc[ln][k] * 48 + c];

    const int dgi = g_deg[i];
    const float dinv_i = (dgi > 0) ? rsqrtf((float)dgi) : 0.f;
    t1[ln][c] = -dinv_i * acc;
    __syncthreads();

    float o = bias[c];
    const float* nrow = nodes + (size_t)i * 48;
    #pragma unroll
    for (int cc = 0; cc < 48; cc++)
        o += nrow[cc] * W0[cc * 48 + c] + t1[ln][cc] * W1[cc * 48 + c];
    out[(size_t)i * 48 + c] = o;
}

// ======================================================================
extern "C" void kernel_launch(void* const* d_in, const int* in_sizes, int n_in,
                              void* d_out, int out_size) {
    const float* x    = (const float*)d_in[0];   // (8,48,64,64)
    const float* W0   = (const float*)d_in[1];   // (48,48)
    const float* W1   = (const float*)d_in[2];   // (48,48)
    const float* bias = (const float*)d_in[3];   // (48,)
    float* out = (float*)d_out;                  // (32768,48)

    k1_normalize<<<NB / 128, 128>>>(x);
    k2_knn<<<NB / 128, 128>>>();
    k5_output<<<NB / 4, 192>>>(W0, W1, bias, out);
}